// round 12
// baseline (speedup 1.0000x reference)
#include <cuda_runtime.h>
#include <cstdint>

#define MAX_NODES 100000
#define MAX_EDGES 1600000
#define SCAN_BLK 1024
#define MAX_SCAN_BLOCKS 128

// Scratch (static device globals; zero-initialized at load; node2 restores zeros)
__device__ int g_count[MAX_NODES];
__device__ int g_cursor[MAX_NODES];
__device__ int g_start[MAX_NODES];
__device__ int g_perm_src[MAX_EDGES];
__device__ unsigned long long g_stat[MAX_SCAN_BLOCKS];
__device__ __align__(16) float4 g_mean[MAX_NODES * 4];   // mean feature, 16 f/node
__device__ __align__(16) float g_y[MAX_NODES * 4];
__device__ __align__(16) float g_z[MAX_NODES * 4];

// ---------------------------------------------------------------------------
// 1) histogram of dst
// ---------------------------------------------------------------------------
__global__ void k_hist(const int* __restrict__ ei, int E, int N) {
    int e = blockIdx.x * blockDim.x + threadIdx.x;
    if (e >= E) return;
    int dst = __ldg(&ei[E + e]);
    if ((unsigned)dst < (unsigned)N) atomicAdd(&g_count[dst], 1);
}

// ---------------------------------------------------------------------------
// 2) single-pass exclusive scan (decoupled lookback), nb <= 128 blocks
// ---------------------------------------------------------------------------
__device__ __forceinline__ void stat_store(unsigned long long* p, unsigned long long v) {
    asm volatile("st.global.release.gpu.u64 [%0], %1;" :: "l"(p), "l"(v) : "memory");
}
__device__ __forceinline__ unsigned long long stat_load(const unsigned long long* p) {
    unsigned long long v;
    asm volatile("ld.global.acquire.gpu.u64 %0, [%1];" : "=l"(v) : "l"(p) : "memory");
    return v;
}

__global__ void __launch_bounds__(SCAN_BLK) k_scan(int N) {
    __shared__ int wsum[32];
    __shared__ int s_base;
    int tid = threadIdx.x, bid = blockIdx.x;
    int lane = tid & 31, wid = tid >> 5;
    int i = bid * SCAN_BLK + tid;
    int v = (i < N) ? g_count[i] : 0;

    int incl = v;
#pragma unroll
    for (int off = 1; off < 32; off <<= 1) {
        int t = __shfl_up_sync(0xffffffffu, incl, off);
        if (lane >= off) incl += t;
    }
    if (lane == 31) wsum[wid] = incl;
    __syncthreads();

    int total = 0;
    if (wid == 0) {
        int wv = wsum[lane];
        int winc = wv;
#pragma unroll
        for (int off = 1; off < 32; off <<= 1) {
            int t = __shfl_up_sync(0xffffffffu, winc, off);
            if (lane >= off) winc += t;
        }
        wsum[lane] = winc - wv;
        total = __shfl_sync(0xffffffffu, winc, 31);
        if (lane == 0) {
            unsigned long long pk = ((unsigned long long)(unsigned)total << 32)
                                  | (bid == 0 ? 2ull : 1ull);
            stat_store(&g_stat[bid], pk);
            if (bid == 0) s_base = 0;
        }
        if (bid > 0) {
            int look = bid - 1;
            int running = 0;
            while (true) {
                int idx = look - lane;
                int flag, val;
                unsigned long long pk;
                while (true) {
                    if (idx >= 0) {
                        pk = stat_load(&g_stat[idx]);
                        flag = (int)(pk & 3ull);
                        val  = (int)(pk >> 32);
                    } else { flag = 2; val = 0; }
                    if (!__any_sync(0xffffffffu, flag == 0)) break;
                    __nanosleep(20);
                }
                unsigned m = __ballot_sync(0xffffffffu, flag == 2);
                int contrib;
                if (m) {
                    int first = __ffs(m) - 1;
                    contrib = (lane <= first) ? val : 0;
                } else {
                    contrib = val;
                }
#pragma unroll
                for (int off = 16; off > 0; off >>= 1)
                    contrib += __shfl_down_sync(0xffffffffu, contrib, off);
                contrib = __shfl_sync(0xffffffffu, contrib, 0);
                running += contrib;
                if (m) break;
                look -= 32;
            }
            if (lane == 0) {
                unsigned long long pk =
                    ((unsigned long long)(unsigned)(running + total) << 32) | 2ull;
                stat_store(&g_stat[bid], pk);
                s_base = running;
            }
        }
    }
    __syncthreads();
    if (i < N) g_start[i] = s_base + wsum[wid] + (incl - v);
}

// ---------------------------------------------------------------------------
// 3) scatter src ids into dst-sorted order
// ---------------------------------------------------------------------------
__global__ void k_scatter(const int* __restrict__ ei, int E, int N) {
    int e = blockIdx.x * blockDim.x + threadIdx.x;
    if (e >= E) return;
    int src = __ldg(&ei[e]);
    int dst = __ldg(&ei[E + e]);
    if ((unsigned)src >= (unsigned)N || (unsigned)dst >= (unsigned)N) return;
    int pos = g_start[dst] + atomicAdd(&g_cursor[dst], 1);
    g_perm_src[pos] = src;
}

// ---------------------------------------------------------------------------
// 4a) gather-mean: 8 lanes per node (2 edge-groups x 4 comps). Each lane
//     privately sums one float4 quarter-row over its half of the edges,
//     then one shfl(4) combines the two edge-groups. 800k threads.
// ---------------------------------------------------------------------------
__global__ void __launch_bounds__(256) k_gather(const float4* __restrict__ feat4,
                                                int N) {
    long long gid = (long long)blockIdx.x * blockDim.x + threadIdx.x;
    int n = (int)(gid >> 3);
    int sub = (int)(gid & 7);
    if (n >= N) return;
    int comp = sub & 3;       // float4 quarter
    int egrp = sub >> 2;      // 0 or 1

    int deg = g_count[n];
    int start = g_start[n];

    float4 acc = make_float4(0.f, 0.f, 0.f, 0.f);
    int j = egrp;
    // unroll-4 over stride-2 edge walk: 4 independent chains in flight
    for (; j + 6 < deg; j += 8) {
        int s0 = __ldg(&g_perm_src[start + j]);
        int s1 = __ldg(&g_perm_src[start + j + 2]);
        int s2 = __ldg(&g_perm_src[start + j + 4]);
        int s3 = __ldg(&g_perm_src[start + j + 6]);
        float4 v0 = __ldg(&feat4[(size_t)s0 * 4 + comp]);
        float4 v1 = __ldg(&feat4[(size_t)s1 * 4 + comp]);
        float4 v2 = __ldg(&feat4[(size_t)s2 * 4 + comp]);
        float4 v3 = __ldg(&feat4[(size_t)s3 * 4 + comp]);
        acc.x += v0.x + v1.x + v2.x + v3.x;
        acc.y += v0.y + v1.y + v2.y + v3.y;
        acc.z += v0.z + v1.z + v2.z + v3.z;
        acc.w += v0.w + v1.w + v2.w + v3.w;
    }
    for (; j < deg; j += 2) {
        int s = __ldg(&g_perm_src[start + j]);
        float4 v = __ldg(&feat4[(size_t)s * 4 + comp]);
        acc.x += v.x; acc.y += v.y; acc.z += v.z; acc.w += v.w;
    }
    // combine the two edge-groups (lanes differ by 4)
    acc.x += __shfl_down_sync(0xffffffffu, acc.x, 4, 8);
    acc.y += __shfl_down_sync(0xffffffffu, acc.y, 4, 8);
    acc.z += __shfl_down_sync(0xffffffffu, acc.z, 4, 8);
    acc.w += __shfl_down_sync(0xffffffffu, acc.w, 4, 8);
    if (egrp == 0) {
        float invd = 1.0f / fmaxf((float)deg, 1.0f);
        acc.x *= invd; acc.y *= invd; acc.z *= invd; acc.w *= invd;
        g_mean[(size_t)n * 4 + comp] = acc;
    }
}

// ---------------------------------------------------------------------------
// 4b) GEMM + fold. Block = 256 thr = 8 warps; 128 nodes/block (two passes of
//     8 nodes/warp over the same staged weights -> half the staging traffic).
//     Lane owns cols 4*lane..4*lane+3; per k: 2 LDS.128 reused by 8 nodes.
// ---------------------------------------------------------------------------
__global__ void __launch_bounds__(256) k_gemm(
        const float4* __restrict__ feat4,
        const float4* __restrict__ W1l4,   // 16 x 32 float4
        const float4* __restrict__ b1_4,   // 32 float4
        const float4* __restrict__ W1r4,   // 16 x 32 float4
        const float4* __restrict__ W2l4,   // 96 float4
        const float4* __restrict__ W2r4,
        int N) {
    __shared__ __align__(16) float sW1l[16 * 128];
    __shared__ __align__(16) float sW1r[16 * 128];
    __shared__ __align__(16) float sMF[128 * 32];  // per node: [0..15]=mean, [16..31]=feat

    int tid = threadIdx.x;
    int lane = tid & 31;
    int warp = tid >> 5;
    int n0 = blockIdx.x * 128;

    // coop stage W1 (1024 float4s over 256 threads)
    {
        float4* dl = (float4*)sW1l;
        float4* dr = (float4*)sW1r;
#pragma unroll
        for (int i = 0; i < 2; i++) {
            dl[tid + i * 256] = __ldg(&W1l4[tid + i * 256]);
            dr[tid + i * 256] = __ldg(&W1r4[tid + i * 256]);
        }
    }
    // coop stage mean+feat: 128 nodes x 4 comps = 512 slots over 256 threads
    {
#pragma unroll
        for (int i = 0; i < 2; i++) {
            int slot = tid + i * 256;
            int ln = slot >> 2, comp = slot & 3;
            int nn = n0 + ln;
            if (nn < N) {
                *(float4*)&sMF[ln * 32 + comp * 4]      = g_mean[(size_t)nn * 4 + comp];
                *(float4*)&sMF[ln * 32 + 16 + comp * 4] = __ldg(&feat4[(size_t)nn * 4 + comp]);
            }
        }
    }
    __syncthreads();

    float4 bb = __ldg(&b1_4[lane]);
    float4 l0 = __ldg(&W2l4[lane * 3 + 0]);
    float4 l1 = __ldg(&W2l4[lane * 3 + 1]);
    float4 l2 = __ldg(&W2l4[lane * 3 + 2]);
    float4 r0 = __ldg(&W2r4[lane * 3 + 0]);
    float4 r1 = __ldg(&W2r4[lane * 3 + 1]);
    float4 r2 = __ldg(&W2r4[lane * 3 + 2]);

#pragma unroll 1
    for (int pass = 0; pass < 2; pass++) {
        int nbase = pass * 64 + warp * 8;
        float4 a[8];
#pragma unroll
        for (int t = 0; t < 8; t++) a[t] = bb;

#pragma unroll
        for (int k = 0; k < 16; k++) {
            float4 wl = *(float4*)&sW1l[k * 128 + lane * 4];
            float4 wr = *(float4*)&sW1r[k * 128 + lane * 4];
#pragma unroll
            for (int t = 0; t < 8; t++) {
                float mk = sMF[(nbase + t) * 32 + k];
                float fk = sMF[(nbase + t) * 32 + 16 + k];
                a[t].x = fmaf(mk, wl.x, fmaf(fk, wr.x, a[t].x));
                a[t].y = fmaf(mk, wl.y, fmaf(fk, wr.y, a[t].y));
                a[t].z = fmaf(mk, wl.z, fmaf(fk, wr.z, a[t].z));
                a[t].w = fmaf(mk, wl.w, fmaf(fk, wr.w, a[t].w));
            }
        }

#pragma unroll
        for (int t = 0; t < 8; t++) {
            float ax = fmaxf(a[t].x, 0.f), ay = fmaxf(a[t].y, 0.f);
            float az = fmaxf(a[t].z, 0.f), aw = fmaxf(a[t].w, 0.f);

            float py0 = ax * l0.x + ay * l0.w + az * l1.z + aw * l2.y;
            float py1 = ax * l0.y + ay * l1.x + az * l1.w + aw * l2.z;
            float py2 = ax * l0.z + ay * l1.y + az * l2.x + aw * l2.w;
            float pz0 = ax * r0.x + ay * r0.w + az * r1.z + aw * r2.y;
            float pz1 = ax * r0.y + ay * r1.x + az * r1.w + aw * r2.z;
            float pz2 = ax * r0.z + ay * r1.y + az * r2.x + aw * r2.w;

#pragma unroll
            for (int off = 16; off > 0; off >>= 1) {
                py0 += __shfl_down_sync(0xffffffffu, py0, off);
                py1 += __shfl_down_sync(0xffffffffu, py1, off);
                py2 += __shfl_down_sync(0xffffffffu, py2, off);
                pz0 += __shfl_down_sync(0xffffffffu, pz0, off);
                pz1 += __shfl_down_sync(0xffffffffu, pz1, off);
                pz2 += __shfl_down_sync(0xffffffffu, pz2, off);
            }
            int nn = n0 + nbase + t;
            if (lane == 0 && nn < N) {
                *(float4*)&g_y[(size_t)nn * 4] = make_float4(py0, py1, py2, 0.f);
                *(float4*)&g_z[(size_t)nn * 4] = make_float4(pz0, pz1, pz2, 0.f);
            }
        }
    }
}

// ---------------------------------------------------------------------------
// 5) fused layer-2: 8 lanes/node gather-mean of y + epilogue; restores zeros.
// ---------------------------------------------------------------------------
__global__ void __launch_bounds__(256) k_node2(const float* __restrict__ b2,
                                               float* __restrict__ out, int N) {
    int tid = threadIdx.x;
    if (tid == 0 && blockIdx.x < MAX_SCAN_BLOCKS) g_stat[blockIdx.x] = 0ull;
    long long gid = (long long)blockIdx.x * blockDim.x + tid;
    int n = (int)(gid >> 3);
    int sub = (int)(gid & 7);
    if (n >= N) return;

    int deg = g_count[n];
    int start = g_start[n];

    float ax = 0.f, ay = 0.f, az = 0.f;
    for (int j = sub; j < deg; j += 8) {
        int src = __ldg(&g_perm_src[start + j]);
        float4 v = *(const float4*)&g_y[(size_t)src * 4];
        ax += v.x; ay += v.y; az += v.z;
    }
#pragma unroll
    for (int off = 4; off > 0; off >>= 1) {
        ax += __shfl_down_sync(0xffffffffu, ax, off, 8);
        ay += __shfl_down_sync(0xffffffffu, ay, off, 8);
        az += __shfl_down_sync(0xffffffffu, az, off, 8);
    }
    if (sub == 0) {
        float invd = 1.0f / fmaxf((float)deg, 1.0f);
        float4 z = *(const float4*)&g_z[(size_t)n * 4];
        out[(size_t)n * 3 + 0] = ax * invd + __ldg(&b2[0]) + z.x;
        out[(size_t)n * 3 + 1] = ay * invd + __ldg(&b2[1]) + z.y;
        out[(size_t)n * 3 + 2] = az * invd + __ldg(&b2[2]) + z.z;
        g_count[n] = 0;
        g_cursor[n] = 0;
    }
}

// ---------------------------------------------------------------------------
extern "C" void kernel_launch(void* const* d_in, const int* in_sizes, int n_in,
                              void* d_out, int out_size) {
    const float* feature = (const float*)d_in[0];
    const int*   ei      = (const int*)d_in[1];   // int32 (JAX x64 disabled)
    // d_in[2] = edge_type (unused)
    const float* W1l = (const float*)d_in[3];
    const float* b1  = (const float*)d_in[4];
    const float* W1r = (const float*)d_in[5];
    const float* W2l = (const float*)d_in[6];
    const float* b2  = (const float*)d_in[7];
    const float* W2r = (const float*)d_in[8];
    float* out = (float*)d_out;

    int N = in_sizes[0] / 16;
    int E = in_sizes[1] / 2;
    int nb = (N + SCAN_BLK - 1) / SCAN_BLK;

    k_hist<<<(E + 255) / 256, 256>>>(ei, E, N);
    k_scan<<<nb, SCAN_BLK>>>(N);
    k_scatter<<<(E + 255) / 256, 256>>>(ei, E, N);
    k_gather<<<(int)((8LL * N + 255) / 256), 256>>>((const float4*)feature, N);
    k_gemm<<<(N + 127) / 128, 256>>>((const float4*)feature,
                                     (const float4*)W1l, (const float4*)b1,
                                     (const float4*)W1r, (const float4*)W2l,
                                     (const float4*)W2r, N);
    k_node2<<<(int)((8LL * N + 255) / 256), 256>>>(b2, out, N);
}

// round 14
// speedup vs baseline: 1.0609x; 1.0609x over previous
#include <cuda_runtime.h>
#include <cstdint>

#define MAX_NODES 100000
#define MAX_EDGES 1600000
#define SCAN_BLK 1024
#define MAX_SCAN_BLOCKS 128

// Scratch (static device globals; zero-initialized at load; node2 restores zeros)
__device__ int g_count[MAX_NODES];
__device__ int g_start[MAX_NODES];
__device__ int g_rank[MAX_EDGES];        // edge rank within its dst bucket
__device__ int g_perm_src[MAX_EDGES];    // src ids, dst-sorted
__device__ unsigned long long g_stat[MAX_SCAN_BLOCKS];
__device__ __align__(16) float4 g_mean[MAX_NODES * 4];   // mean feature, 16 f/node
__device__ __align__(16) float g_y[MAX_NODES * 4];
__device__ __align__(16) float g_z[MAX_NODES * 4];

// ---------------------------------------------------------------------------
// 1) histogram of dst + record per-edge rank (atomicAdd return value)
// ---------------------------------------------------------------------------
__global__ void k_hist(const int* __restrict__ ei, int E, int N) {
    int e = blockIdx.x * blockDim.x + threadIdx.x;
    if (e >= E) return;
    int dst = __ldg(&ei[E + e]);
    if ((unsigned)dst < (unsigned)N) {
        int r = atomicAdd(&g_count[dst], 1);
        g_rank[e] = r;
    }
}

// ---------------------------------------------------------------------------
// 2) single-pass exclusive scan (decoupled lookback), nb <= 128 blocks
// ---------------------------------------------------------------------------
__device__ __forceinline__ void stat_store(unsigned long long* p, unsigned long long v) {
    asm volatile("st.global.release.gpu.u64 [%0], %1;" :: "l"(p), "l"(v) : "memory");
}
__device__ __forceinline__ unsigned long long stat_load(const unsigned long long* p) {
    unsigned long long v;
    asm volatile("ld.global.acquire.gpu.u64 %0, [%1];" : "=l"(v) : "l"(p) : "memory");
    return v;
}

__global__ void __launch_bounds__(SCAN_BLK) k_scan(int N) {
    __shared__ int wsum[32];
    __shared__ int s_base;
    int tid = threadIdx.x, bid = blockIdx.x;
    int lane = tid & 31, wid = tid >> 5;
    int i = bid * SCAN_BLK + tid;
    int v = (i < N) ? g_count[i] : 0;

    int incl = v;
#pragma unroll
    for (int off = 1; off < 32; off <<= 1) {
        int t = __shfl_up_sync(0xffffffffu, incl, off);
        if (lane >= off) incl += t;
    }
    if (lane == 31) wsum[wid] = incl;
    __syncthreads();

    int total = 0;
    if (wid == 0) {
        int wv = wsum[lane];
        int winc = wv;
#pragma unroll
        for (int off = 1; off < 32; off <<= 1) {
            int t = __shfl_up_sync(0xffffffffu, winc, off);
            if (lane >= off) winc += t;
        }
        wsum[lane] = winc - wv;
        total = __shfl_sync(0xffffffffu, winc, 31);
        if (lane == 0) {
            unsigned long long pk = ((unsigned long long)(unsigned)total << 32)
                                  | (bid == 0 ? 2ull : 1ull);
            stat_store(&g_stat[bid], pk);
            if (bid == 0) s_base = 0;
        }
        if (bid > 0) {
            int look = bid - 1;
            int running = 0;
            while (true) {
                int idx = look - lane;
                int flag, val;
                unsigned long long pk;
                while (true) {
                    if (idx >= 0) {
                        pk = stat_load(&g_stat[idx]);
                        flag = (int)(pk & 3ull);
                        val  = (int)(pk >> 32);
                    } else { flag = 2; val = 0; }
                    if (!__any_sync(0xffffffffu, flag == 0)) break;
                    __nanosleep(20);
                }
                unsigned m = __ballot_sync(0xffffffffu, flag == 2);
                int contrib;
                if (m) {
                    int first = __ffs(m) - 1;
                    contrib = (lane <= first) ? val : 0;
                } else {
                    contrib = val;
                }
#pragma unroll
                for (int off = 16; off > 0; off >>= 1)
                    contrib += __shfl_down_sync(0xffffffffu, contrib, off);
                contrib = __shfl_sync(0xffffffffu, contrib, 0);
                running += contrib;
                if (m) break;
                look -= 32;
            }
            if (lane == 0) {
                unsigned long long pk =
                    ((unsigned long long)(unsigned)(running + total) << 32) | 2ull;
                stat_store(&g_stat[bid], pk);
                s_base = running;
            }
        }
    }
    __syncthreads();
    if (i < N) g_start[i] = s_base + wsum[wid] + (incl - v);
}

// ---------------------------------------------------------------------------
// 3) scatter src ids into dst-sorted order (atomic-free: rank precomputed)
// ---------------------------------------------------------------------------
__global__ void k_scatter(const int* __restrict__ ei, int E, int N) {
    int e = blockIdx.x * blockDim.x + threadIdx.x;
    if (e >= E) return;
    int src = __ldg(&ei[e]);
    int dst = __ldg(&ei[E + e]);
    if ((unsigned)src >= (unsigned)N || (unsigned)dst >= (unsigned)N) return;
    int pos = g_start[dst] + g_rank[e];
    g_perm_src[pos] = src;
}

// ---------------------------------------------------------------------------
// 4a) gather-mean: 16 lanes per node (4 edge-groups x 4 comps). Each lane
//     privately sums one float4 quarter-row over its quarter of the edges;
//     shfl_down(8,4) within width-16 combines groups. 1.6M threads.
// ---------------------------------------------------------------------------
__global__ void __launch_bounds__(256) k_gather(const float4* __restrict__ feat4,
                                                int N) {
    long long gid = (long long)blockIdx.x * blockDim.x + threadIdx.x;
    int n = (int)(gid >> 4);
    int sub = (int)(gid & 15);
    if (n >= N) return;
    int comp = sub & 3;       // float4 quarter
    int egrp = sub >> 2;      // 0..3

    int deg = g_count[n];
    int start = g_start[n];

    float4 acc = make_float4(0.f, 0.f, 0.f, 0.f);
    int j = egrp;
    for (; j + 4 < deg; j += 8) {
        int s0 = __ldg(&g_perm_src[start + j]);
        int s1 = __ldg(&g_perm_src[start + j + 4]);
        float4 v0 = __ldg(&feat4[(size_t)s0 * 4 + comp]);
        float4 v1 = __ldg(&feat4[(size_t)s1 * 4 + comp]);
        acc.x += v0.x + v1.x;
        acc.y += v0.y + v1.y;
        acc.z += v0.z + v1.z;
        acc.w += v0.w + v1.w;
    }
    for (; j < deg; j += 4) {
        int s = __ldg(&g_perm_src[start + j]);
        float4 v = __ldg(&feat4[(size_t)s * 4 + comp]);
        acc.x += v.x; acc.y += v.y; acc.z += v.z; acc.w += v.w;
    }
    // combine the four edge-groups (lanes differ by 4 within width-16)
#pragma unroll
    for (int off = 8; off >= 4; off >>= 1) {
        acc.x += __shfl_down_sync(0xffffffffu, acc.x, off, 16);
        acc.y += __shfl_down_sync(0xffffffffu, acc.y, off, 16);
        acc.z += __shfl_down_sync(0xffffffffu, acc.z, off, 16);
        acc.w += __shfl_down_sync(0xffffffffu, acc.w, off, 16);
    }
    if (egrp == 0) {
        float invd = 1.0f / fmaxf((float)deg, 1.0f);
        acc.x *= invd; acc.y *= invd; acc.z *= invd; acc.w *= invd;
        g_mean[(size_t)n * 4 + comp] = acc;
    }
}

// ---------------------------------------------------------------------------
// 4b) GEMM + fold. Block = 256 thr = 8 warps = 64 nodes (8 per warp).
//     W1 staged in smem once per block; mean/feat staged via coalesced loads.
// ---------------------------------------------------------------------------
__global__ void __launch_bounds__(256) k_gemm(
        const float4* __restrict__ feat4,
        const float4* __restrict__ W1l4,   // 16 x 32 float4
        const float4* __restrict__ b1_4,   // 32 float4
        const float4* __restrict__ W1r4,   // 16 x 32 float4
        const float4* __restrict__ W2l4,   // 96 float4
        const float4* __restrict__ W2r4,
        int N) {
    __shared__ __align__(16) float sW1l[16 * 128];
    __shared__ __align__(16) float sW1r[16 * 128];
    __shared__ __align__(16) float sMF[64 * 32];   // [0..15]=mean, [16..31]=feat

    int tid = threadIdx.x;
    int lane = tid & 31;
    int warp = tid >> 5;
    int n0 = blockIdx.x * 64;

    {
        float4* dl = (float4*)sW1l;
        float4* dr = (float4*)sW1r;
#pragma unroll
        for (int i = 0; i < 2; i++) {
            dl[tid + i * 256] = __ldg(&W1l4[tid + i * 256]);
            dr[tid + i * 256] = __ldg(&W1r4[tid + i * 256]);
        }
    }
    {
        int ln = tid >> 2, comp = tid & 3;
        int nn = n0 + ln;
        if (nn < N) {
            *(float4*)&sMF[ln * 32 + comp * 4]      = g_mean[(size_t)nn * 4 + comp];
            *(float4*)&sMF[ln * 32 + 16 + comp * 4] = __ldg(&feat4[(size_t)nn * 4 + comp]);
        }
    }
    __syncthreads();

    int nbase = warp * 8;
    float4 bb = __ldg(&b1_4[lane]);
    float4 a[8];
#pragma unroll
    for (int t = 0; t < 8; t++) a[t] = bb;

#pragma unroll
    for (int k = 0; k < 16; k++) {
        float4 wl = *(float4*)&sW1l[k * 128 + lane * 4];
        float4 wr = *(float4*)&sW1r[k * 128 + lane * 4];
#pragma unroll
        for (int t = 0; t < 8; t++) {
            float mk = sMF[(nbase + t) * 32 + k];
            float fk = sMF[(nbase + t) * 32 + 16 + k];
            a[t].x = fmaf(mk, wl.x, fmaf(fk, wr.x, a[t].x));
            a[t].y = fmaf(mk, wl.y, fmaf(fk, wr.y, a[t].y));
            a[t].z = fmaf(mk, wl.z, fmaf(fk, wr.z, a[t].z));
            a[t].w = fmaf(mk, wl.w, fmaf(fk, wr.w, a[t].w));
        }
    }

    float4 l0 = __ldg(&W2l4[lane * 3 + 0]);
    float4 l1 = __ldg(&W2l4[lane * 3 + 1]);
    float4 l2 = __ldg(&W2l4[lane * 3 + 2]);
    float4 r0 = __ldg(&W2r4[lane * 3 + 0]);
    float4 r1 = __ldg(&W2r4[lane * 3 + 1]);
    float4 r2 = __ldg(&W2r4[lane * 3 + 2]);

#pragma unroll
    for (int t = 0; t < 8; t++) {
        float ax = fmaxf(a[t].x, 0.f), ay = fmaxf(a[t].y, 0.f);
        float az = fmaxf(a[t].z, 0.f), aw = fmaxf(a[t].w, 0.f);

        float py0 = ax * l0.x + ay * l0.w + az * l1.z + aw * l2.y;
        float py1 = ax * l0.y + ay * l1.x + az * l1.w + aw * l2.z;
        float py2 = ax * l0.z + ay * l1.y + az * l2.x + aw * l2.w;
        float pz0 = ax * r0.x + ay * r0.w + az * r1.z + aw * r2.y;
        float pz1 = ax * r0.y + ay * r1.x + az * r1.w + aw * r2.z;
        float pz2 = ax * r0.z + ay * r1.y + az * r2.x + aw * r2.w;

#pragma unroll
        for (int off = 16; off > 0; off >>= 1) {
            py0 += __shfl_down_sync(0xffffffffu, py0, off);
            py1 += __shfl_down_sync(0xffffffffu, py1, off);
            py2 += __shfl_down_sync(0xffffffffu, py2, off);
            pz0 += __shfl_down_sync(0xffffffffu, pz0, off);
            pz1 += __shfl_down_sync(0xffffffffu, pz1, off);
            pz2 += __shfl_down_sync(0xffffffffu, pz2, off);
        }
        int nn = n0 + nbase + t;
        if (lane == 0 && nn < N) {
            *(float4*)&g_y[(size_t)nn * 4] = make_float4(py0, py1, py2, 0.f);
            *(float4*)&g_z[(size_t)nn * 4] = make_float4(pz0, pz1, pz2, 0.f);
        }
    }
}

// ---------------------------------------------------------------------------
// 5) fused layer-2: 8 lanes/node gather-mean of y + epilogue; restores zeros.
// ---------------------------------------------------------------------------
__global__ void __launch_bounds__(256) k_node2(const float* __restrict__ b2,
                                               float* __restrict__ out, int N) {
    int tid = threadIdx.x;
    if (tid == 0 && blockIdx.x < MAX_SCAN_BLOCKS) g_stat[blockIdx.x] = 0ull;
    long long gid = (long long)blockIdx.x * blockDim.x + tid;
    int n = (int)(gid >> 3);
    int sub = (int)(gid & 7);
    if (n >= N) return;

    int deg = g_count[n];
    int start = g_start[n];

    float ax = 0.f, ay = 0.f, az = 0.f;
    for (int j = sub; j < deg; j += 8) {
        int src = __ldg(&g_perm_src[start + j]);
        float4 v = *(const float4*)&g_y[(size_t)src * 4];
        ax += v.x; ay += v.y; az += v.z;
    }
#pragma unroll
    for (int off = 4; off > 0; off >>= 1) {
        ax += __shfl_down_sync(0xffffffffu, ax, off, 8);
        ay += __shfl_down_sync(0xffffffffu, ay, off, 8);
        az += __shfl_down_sync(0xffffffffu, az, off, 8);
    }
    if (sub == 0) {
        float invd = 1.0f / fmaxf((float)deg, 1.0f);
        float4 z = *(const float4*)&g_z[(size_t)n * 4];
        out[(size_t)n * 3 + 0] = ax * invd + __ldg(&b2[0]) + z.x;
        out[(size_t)n * 3 + 1] = ay * invd + __ldg(&b2[1]) + z.y;
        out[(size_t)n * 3 + 2] = az * invd + __ldg(&b2[2]) + z.z;
        g_count[n] = 0;      // restore zero-invariant for next replay
    }
}

// ---------------------------------------------------------------------------
extern "C" void kernel_launch(void* const* d_in, const int* in_sizes, int n_in,
                              void* d_out, int out_size) {
    const float* feature = (const float*)d_in[0];
    const int*   ei      = (const int*)d_in[1];   // int32 (JAX x64 disabled)
    // d_in[2] = edge_type (unused)
    const float* W1l = (const float*)d_in[3];
    const float* b1  = (const float*)d_in[4];
    const float* W1r = (const float*)d_in[5];
    const float* W2l = (const float*)d_in[6];
    const float* b2  = (const float*)d_in[7];
    const float* W2r = (const float*)d_in[8];
    float* out = (float*)d_out;

    int N = in_sizes[0] / 16;
    int E = in_sizes[1] / 2;
    int nb = (N + SCAN_BLK - 1) / SCAN_BLK;

    k_hist<<<(E + 255) / 256, 256>>>(ei, E, N);
    k_scan<<<nb, SCAN_BLK>>>(N);
    k_scatter<<<(E + 255) / 256, 256>>>(ei, E, N);
    k_gather<<<(int)((16LL * N + 255) / 256), 256>>>((const float4*)feature, N);
    k_gemm<<<(N + 63) / 64, 256>>>((const float4*)feature,
                                   (const float4*)W1l, (const float4*)b1,
                                   (const float4*)W1r, (const float4*)W2l,
                                   (const float4*)W2r, N);
    k_node2<<<(int)((8LL * N + 255) / 256), 256>>>(b2, out, N);
}